// round 5
// baseline (speedup 1.0000x reference)
#include <cuda_runtime.h>
#include <cuda_bf16.h>
#include <stdint.h>

// Problem constants (fixed by the dataset)
#define B_   8
#define M_   50000
#define D_   256
#define NH_  8
#define GH_  16
#define OUT_ 256
#define SEL_CAP 2048

#define TILE_ROWS 256
#define TILES_PER_B 196              // ceil(50000/256)
#define NTILES (TILES_PER_B * B_)    // 1568
#define CSTRIDE 33                   // padded row stride in floats (conflict-free)

// ---------------- scratch (device globals; no allocations) ----------------
__device__ __align__(16) float g_S[B_ * M_];
__device__ __align__(16) float g_colsum[B_ * D_];
__device__ float g_kth[B_];
__device__ int   g_selCount[B_];
__device__ int   g_selIdx[B_ * SEL_CAP];
__device__ __align__(16) float g_num[B_ * OUT_];
__device__ float g_den[B_ * NH_];

// ---------------- helpers ----------------
__device__ __forceinline__ unsigned keyOf(float x) {
    unsigned u = __float_as_uint(x);
    return (u & 0x80000000u) ? ~u : (u | 0x80000000u);
}
__device__ __forceinline__ float invKey(unsigned k) {
    unsigned u = (k & 0x80000000u) ? (k & 0x7FFFFFFFu) : ~k;
    return __uint_as_float(u);
}

// f32x2 packed FMA (Blackwell sm_103a)
#define FMA2(acc, a, b) asm("fma.rn.f32x2 %0, %1, %2, %0;" : "+l"(acc) : "l"(a), "l"(b))
__device__ __forceinline__ unsigned long long packdup(float x) {
    unsigned long long r;
    unsigned xu = __float_as_uint(x);
    asm("mov.b64 %0, {%1, %1};" : "=l"(r) : "r"(xu));
    return r;
}

// ---------------- Z: zero scratch (3 kernels -> shifts k1 into ncu slots 4-6)
__global__ void z_colsum() {
    int i = blockIdx.x * 256 + threadIdx.x;
    if (i < B_ * D_) g_colsum[i] = 0.f;
}
__global__ void z_num() {
    int i = blockIdx.x * 256 + threadIdx.x;
    if (i < B_ * OUT_) g_num[i] = 0.f;
}
__global__ void z_misc() {
    int i = threadIdx.x;
    if (i < B_ * NH_) g_den[i] = 0.f;
    if (i < B_)       g_selCount[i] = 0;
}

// ---------------- K1: gate scores S + column sums (lane-owns-row design) ---
// One block = one 256-row tile of one batch. 8 chunks of 32 columns:
//   stage chunk into smem (coalesced LDG.128, padded stride 33),
//   each thread accumulates its own row's 16 hidden units (8 x f32x2),
//   weights read as LDS.128 broadcasts (warp-uniform address).
// No cross-lane shuffles; coalesced S store; colsum from staged tile.
__global__ __launch_bounds__(256, 3) void k1_gate(
    const float* __restrict__ h,
    const float* __restrict__ gsl1_w, const float* __restrict__ gsl1_b,
    const float* __restrict__ gsl2_w, const float* __restrict__ gsl2_b,
    int tile0)
{
    __shared__ float st[TILE_ROWS * CSTRIDE];           // 33792 B
    __shared__ unsigned long long ws_ch[32 * 8];        // 2048 B (this chunk's weights)
    __shared__ float csum1[D_];                         // 1024 B

    const int tid  = threadIdx.x;
    const int tile = tile0 + blockIdx.x;
    const int b    = tile / TILES_PER_B;
    const int row0 = (tile % TILES_PER_B) * TILE_ROWS;
    const int grow = row0 + tid;                        // this thread's global row

    csum1[tid] = 0.f;

    const float* hb = h + (size_t)b * M_ * D_;
    const unsigned long long* gw = (const unsigned long long*)gsl1_w; // [256][8] u64 pairs

    unsigned long long acc[8];
#pragma unroll
    for (int p = 0; p < 8; p++) acc[p] = 0ULL;

    for (int ch = 0; ch < 8; ++ch) {
        const int c0 = ch * 32;
        __syncthreads();   // previous chunk's consumers done (also covers csum1 init)

        // stage weights for this chunk: 256 u64
        ws_ch[tid] = gw[c0 * 8 + tid];

        // stage h chunk: 256 rows x 32 cols, coalesced float4 loads
#pragma unroll
        for (int j = 0; j < 8; ++j) {
            int f = tid + 256 * j;            // float4 id
            int r = f >> 3;                   // row in tile
            int q = (f & 7) << 2;             // col offset (0,4,...,28)
            int gr = row0 + r;
            float4 v = make_float4(0.f, 0.f, 0.f, 0.f);
            if (gr < M_) v = *(const float4*)(hb + (size_t)gr * D_ + c0 + q);
            float* dst = &st[r * CSTRIDE + q];
            dst[0] = v.x; dst[1] = v.y; dst[2] = v.z; dst[3] = v.w;
        }
        __syncthreads();

        // compute: this thread's row, 32 columns, 8 packed hidden pairs
        const float* xr = &st[tid * CSTRIDE];
#pragma unroll
        for (int c = 0; c < 32; ++c) {
            float x = xr[c];
            unsigned long long xx = packdup(x);
            const ulonglong2* wp = (const ulonglong2*)&ws_ch[c * 8];
            ulonglong2 w0 = wp[0], w1 = wp[1], w2 = wp[2], w3 = wp[3];
            FMA2(acc[0], xx, w0.x); FMA2(acc[1], xx, w0.y);
            FMA2(acc[2], xx, w1.x); FMA2(acc[3], xx, w1.y);
            FMA2(acc[4], xx, w2.x); FMA2(acc[5], xx, w2.y);
            FMA2(acc[6], xx, w3.x); FMA2(acc[7], xx, w3.y);
        }

        // column-sum partial: thread sums rows [seg*32, seg*32+32) of col (tid&31)
        {
            int col = tid & 31, seg = tid >> 5;
            float s = 0.f;
            const float* p = &st[(seg * 32) * CSTRIDE + col];
#pragma unroll
            for (int r = 0; r < 32; ++r) s += p[r * CSTRIDE];
            atomicAdd(&csum1[c0 + col], s);
        }
    }
    __syncthreads();

    // epilogue: finish gsl1 bias/relu + gsl2 + sigmoid, coalesced S store
    if (grow < M_) {
        float z = gsl2_b[0];
#pragma unroll
        for (int p = 0; p < 8; ++p) {
            float lo = __uint_as_float((unsigned)(acc[p] & 0xFFFFFFFFu));
            float hi = __uint_as_float((unsigned)(acc[p] >> 32));
            float h0 = fmaxf(lo + gsl1_b[2 * p],     0.f);
            float h1 = fmaxf(hi + gsl1_b[2 * p + 1], 0.f);
            z = fmaf(h0, gsl2_w[2 * p], z);
            z = fmaf(h1, gsl2_w[2 * p + 1], z);
        }
        g_S[(size_t)b * M_ + grow] = 1.0f / (1.0f + expf(-z));
    }

    // flush column sums
    atomicAdd(&g_colsum[b * D_ + tid], csum1[tid]);
}

// ---------------- K2: exact k-th largest of S per batch (radix select) ----
// Uniform trip count per block so __ballot_sync never runs under ragged divergence.
__global__ __launch_bounds__(1024) void k2_select(const int* __restrict__ kptr) {
    const int b = blockIdx.x;
    __shared__ unsigned hist[256];
    __shared__ unsigned sh_prefix;
    __shared__ int sh_kneed;

    int kk = kptr ? *kptr : 500;
    if (kk <= 0 || kk > M_) {
        float kf = __int_as_float(kk);
        if (kf >= 1.f && kf <= (float)M_) kk = (int)kf;
        else kk = kk < 1 ? 1 : M_;
    }
    if (kk > M_) kk = M_;

    if (threadIdx.x == 0) { sh_prefix = 0u; sh_kneed = kk; }
    __syncthreads();

    const float* Sb = &g_S[(size_t)b * M_];
    const int NT = 1024;
    const int ITERS = (M_ + NT - 1) / NT;

    for (int pass = 3; pass >= 0; --pass) {
        for (int i = threadIdx.x; i < 256; i += NT) hist[i] = 0u;
        __syncthreads();
        const unsigned pre = sh_prefix;
        const int shift = pass * 8;
        const unsigned himask = (pass == 3) ? 0u : (0xFFFFFFFFu << (shift + 8));

        for (int it = 0; it < ITERS; ++it) {
            const int i = it * NT + threadIdx.x;
            const bool inb = (i < M_);
            unsigned key = inb ? keyOf(Sb[i]) : 0u;
            bool part = inb && (((key ^ pre) & himask) == 0u);
            unsigned act = __ballot_sync(0xFFFFFFFFu, part);
            if (part) {
                int bin = (key >> shift) & 255;
                unsigned peers = __match_any_sync(act, bin);
                int leader = __ffs(peers) - 1;
                if ((int)(threadIdx.x & 31) == leader)
                    atomicAdd(&hist[bin], (unsigned)__popc(peers));
            }
        }
        __syncthreads();
        if (threadIdx.x == 0) {
            int need = sh_kneed;
            unsigned cum = 0; int bin = 0;
            for (int v = 255; v >= 0; --v) {
                if (cum + hist[v] >= (unsigned)need) { bin = v; break; }
                cum += hist[v];
            }
            sh_prefix = pre | ((unsigned)bin << shift);
            sh_kneed = need - (int)cum;
        }
        __syncthreads();
    }
    if (threadIdx.x == 0) g_kth[b] = invKey(sh_prefix);
}

// ---------------- K3: mask output + gather selected indices ---------------
__global__ void k3_mask(float* __restrict__ outmask) {
    const int b = blockIdx.y;
    const int m = blockIdx.x * 256 + threadIdx.x;
    if (m >= M_) return;
    const int idx = b * M_ + m;
    float s = g_S[idx];
    bool sel = s >= g_kth[b];
    outmask[idx] = sel ? 1.f : 0.f;
    if (sel) {
        int pos = atomicAdd(&g_selCount[b], 1);
        if (pos < SEL_CAP) g_selIdx[b * SEL_CAP + pos] = m;
    }
}

// ---------------- K4: selected-row correction (num / den) -----------------
#define RS 16
__global__ __launch_bounds__(256) void k4_selected(
    const float* __restrict__ h,
    const float* __restrict__ att_w, const float* __restrict__ att_b,
    const float* __restrict__ w_w)
{
    __shared__ float hsh[RS][D_];
    __shared__ float efac[RS][NH_];
    __shared__ float aw[D_ * NH_];

    const int b = blockIdx.y;
    const int tid = threadIdx.x;
    for (int i = tid; i < D_ * NH_; i += 256) aw[i] = att_w[i];

    int cnt = g_selCount[b];
    if (cnt > SEL_CAP) cnt = SEL_CAP;
    const int ngroups = (cnt + RS - 1) / RS;
    const float* hb = h + (size_t)b * M_ * D_;

    for (int g = blockIdx.x; g < ngroups; g += gridDim.x) {
        __syncthreads();
        for (int i = tid; i < RS * D_; i += 256) {
            int r = i >> 8, c = i & 255;
            int si = g * RS + r;
            hsh[r][c] = (si < cnt) ? hb[(size_t)g_selIdx[b * SEL_CAP + si] * D_ + c] : 0.f;
        }
        __syncthreads();
        if (tid < RS * NH_) {
            int r = tid >> 3, hd = tid & 7;
            float s = 0.f;
            for (int c = 0; c < D_; c++) s = fmaf(hsh[r][c], aw[c * NH_ + hd], s);
            float a = fmaxf(s + att_b[hd], 0.f);
            efac[r][hd] = (g * RS + r < cnt) ? (expf(a) - 1.f) : 0.f;
        }
        __syncthreads();

        const int e = tid;
        float acc[RS];
#pragma unroll
        for (int r = 0; r < RS; r++) acc[r] = 0.f;
        for (int c = 0; c < D_; c++) {
            float w = __ldg(&w_w[c * OUT_ + e]);
#pragma unroll
            for (int r = 0; r < RS; r++) acc[r] = fmaf(hsh[r][c], w, acc[r]);
        }
        const int hd = e >> 5;
        float s = 0.f;
#pragma unroll
        for (int r = 0; r < RS; r++) s = fmaf(efac[r][hd], acc[r], s);
        atomicAdd(&g_num[b * OUT_ + e], s);
        if (tid < NH_) {
            float d = 0.f;
#pragma unroll
            for (int r = 0; r < RS; r++) d += efac[r][tid];
            atomicAdd(&g_den[b * NH_ + tid], d);
        }
    }
}

// ---------------- K5: base term + Q_res + combine + normalize -------------
__global__ __launch_bounds__(256) void k5_final(
    const float* __restrict__ w_w,
    const float* __restrict__ res_w, const float* __restrict__ res_b,
    float* __restrict__ out)
{
    const int b = blockIdx.x;
    const int e = threadIdx.x;
    __shared__ float cs[D_];
    __shared__ float red[256];

    cs[e] = g_colsum[b * D_ + e];
    __syncthreads();

    float base = 0.f, qr = 0.f;
#pragma unroll 4
    for (int c = 0; c < D_; c++) {
        float x = cs[c];
        base = fmaf(x, __ldg(&w_w[c * OUT_ + e]), base);
        qr   = fmaf(x, __ldg(&res_w[c * OUT_ + e]), qr);
    }
    qr *= (1.0f / (float)M_);
    float Qres = fmaxf(qr + res_b[e], 0.f);
    float den = (float)M_ + g_den[b * NH_ + (e >> 5)];
    float ov = (base + g_num[b * OUT_ + e]) / den;
    float v = fmaxf(ov + Qres, 0.f);

    red[e] = v; __syncthreads();
    for (int s = 128; s > 0; s >>= 1) {
        if (e < s) red[e] += red[e + s];
        __syncthreads();
    }
    float mean = red[0] * (1.0f / 256.0f);
    __syncthreads();
    float dm = v - mean;
    red[e] = dm * dm; __syncthreads();
    for (int s = 128; s > 0; s >>= 1) {
        if (e < s) red[e] += red[e + s];
        __syncthreads();
    }
    float var = red[0] * (1.0f / 256.0f);
    out[b * OUT_ + e] = dm * rsqrtf(var + 1e-8f);
}

// ---------------- launch -----------------
extern "C" void kernel_launch(void* const* d_in, const int* in_sizes, int n_in,
                              void* d_out, int out_size)
{
    const float* h      = (const float*)d_in[0];
    const float* att_w  = (const float*)d_in[1];
    const float* att_b  = (const float*)d_in[2];
    const float* w_w    = (const float*)d_in[3];
    const float* res_w  = (const float*)d_in[4];
    const float* res_b  = (const float*)d_in[5];
    const float* gsl1_w = (const float*)d_in[6];
    const float* gsl1_b = (const float*)d_in[7];
    const float* gsl2_w = (const float*)d_in[8];
    const float* gsl2_b = (const float*)d_in[9];
    const int*   kptr   = (n_in > 10) ? (const int*)d_in[10] : nullptr;

    float* out  = (float*)d_out;              // [B, 1, OUT] -> 2048 floats
    float* mask = out + B_ * OUT_;            // [B, 1, M]   -> 400000 floats

    // slots 1-3: zeroing (puts k1 in ncu capture slots 4-6)
    z_colsum<<<8, 256>>>();
    z_num<<<8, 256>>>();
    z_misc<<<1, 128>>>();

    // slots 4-6: k1 split over the 1568 tiles
    k1_gate<<<523, 256>>>(h, gsl1_w, gsl1_b, gsl2_w, gsl2_b, 0);
    k1_gate<<<523, 256>>>(h, gsl1_w, gsl1_b, gsl2_w, gsl2_b, 523);
    k1_gate<<<522, 256>>>(h, gsl1_w, gsl1_b, gsl2_w, gsl2_b, 1046);

    k2_select<<<B_, 1024>>>(kptr);
    {
        dim3 grid((M_ + 255) / 256, B_);
        k3_mask<<<grid, 256>>>(mask);
    }
    {
        dim3 grid(16, B_);
        k4_selected<<<grid, 256>>>(h, att_w, att_b, w_w);
    }
    k5_final<<<B_, 256>>>(w_w, res_w, res_b, out);
}

// round 6
// speedup vs baseline: 1.1853x; 1.1853x over previous
#include <cuda_runtime.h>
#include <cuda_bf16.h>
#include <stdint.h>

// Problem constants (fixed by the dataset)
#define B_   8
#define M_   50000
#define D_   256
#define NH_  8
#define GH_  16
#define OUT_ 256
#define SEL_CAP 2048

#define TILE_ROWS 512
#define TILES_PER_B 98               // ceil(50000/512)

// ---------------- scratch (device globals; no allocations) ----------------
__device__ __align__(16) float g_S[B_ * M_];
__device__ __align__(16) float g_colsum[B_ * D_];
__device__ float g_kth[B_];
__device__ int   g_selCount[B_];
__device__ int   g_selIdx[B_ * SEL_CAP];
__device__ __align__(16) float g_num[B_ * OUT_];
__device__ float g_den[B_ * NH_];

// ---------------- helpers ----------------
__device__ __forceinline__ unsigned keyOf(float x) {
    unsigned u = __float_as_uint(x);
    return (u & 0x80000000u) ? ~u : (u | 0x80000000u);
}
__device__ __forceinline__ float invKey(unsigned k) {
    unsigned u = (k & 0x80000000u) ? (k & 0x7FFFFFFFu) : ~k;
    return __uint_as_float(u);
}

// f32x2 packed FMA (Blackwell sm_103a)
#define FMA2(acc, a, b) asm("fma.rn.f32x2 %0, %1, %2, %0;" : "+l"(acc) : "l"(a), "l"(b))
__device__ __forceinline__ unsigned long long packdup(float x) {
    unsigned long long r;
    unsigned xu = __float_as_uint(x);
    asm("mov.b64 %0, {%1, %1};" : "=l"(r) : "r"(xu));
    return r;
}

// ---------------- Z: zero scratch (3 launches; k1 is launch #4) ------------
__global__ void z_colsum() {
    int i = blockIdx.x * 256 + threadIdx.x;
    if (i < B_ * D_) g_colsum[i] = 0.f;
}
__global__ void z_num() {
    int i = blockIdx.x * 256 + threadIdx.x;
    if (i < B_ * OUT_) g_num[i] = 0.f;
}
__global__ void z_misc() {
    int i = threadIdx.x;
    if (i < B_ * NH_) g_den[i] = 0.f;
    if (i < B_)       g_selCount[i] = 0;
}

// ---------------- K1: gate scores S + column sums --------------------------
// Tile = 512 rows x 256 threads (2 rows/thread). 8 chunks of 32 columns:
//  - stage via coalesced LDG.128 into XOR-swizzled float4 smem (conflict-free
//    STS.128 and LDS.128, 16B aligned, zero padding)
//  - column sums accumulated in registers DURING staging (fixed q per thread),
//    flushed as 4 shared atomics per chunk
//  - compute: per 4-col group, 16 broadcast w-LDS.128 amortized over 2 rows
//    -> 64 FMA2 per group; LSU well under FMA pipe.
// Dynamic smem: st4 64KB + ws 2KB + csum 1KB = 68608 B -> 3 blocks/SM.
__global__ __launch_bounds__(256, 3) void k1_gate(
    const float* __restrict__ h,
    const float* __restrict__ gsl1_w, const float* __restrict__ gsl1_b,
    const float* __restrict__ gsl2_w, const float* __restrict__ gsl2_b)
{
    extern __shared__ __align__(16) unsigned char smraw[];
    float4* st4 = (float4*)smraw;                                   // 512*8 float4 = 64KB
    unsigned long long* ws = (unsigned long long*)(smraw + 65536);  // 256 u64 = 2KB
    float* csum1 = (float*)(smraw + 65536 + 2048);                  // 256 f = 1KB

    const int tid  = threadIdx.x;
    const int b    = blockIdx.y;
    const int row0 = blockIdx.x * TILE_ROWS;
    const int sw   = tid & 7;            // this thread's swizzle key / q-octet
    const int q    = sw << 2;            // fixed 4-col window during staging

    csum1[tid] = 0.f;

    const float* hb = h + (size_t)b * M_ * D_;
    const unsigned long long* gw = (const unsigned long long*)gsl1_w; // [256][8] u64

    unsigned long long a0[8], a1[8];
#pragma unroll
    for (int p = 0; p < 8; p++) { a0[p] = 0ULL; a1[p] = 0ULL; }

    for (int ch = 0; ch < 8; ++ch) {
        const int c0 = ch * 32;
        __syncthreads();                 // st4/ws safe to overwrite; csum1 init visible

        ws[tid] = gw[c0 * 8 + tid];      // this chunk's weights (32 cols x 8 u64)

        // stage 512 rows x 32 cols; accumulate column partials in registers
        float4 ca = make_float4(0.f, 0.f, 0.f, 0.f);
#pragma unroll
        for (int j = 0; j < 16; ++j) {
            int f = tid + 256 * j;       // float4 id; f&7 == tid&7 (fixed q)
            int r = f >> 3;              // row in tile
            int gr = row0 + r;
            float4 v = make_float4(0.f, 0.f, 0.f, 0.f);
            if (gr < M_) v = *(const float4*)(hb + (size_t)gr * D_ + c0 + q);
            ca.x += v.x; ca.y += v.y; ca.z += v.z; ca.w += v.w;
            st4[r * 8 + (sw ^ (r & 7))] = v;
        }
        atomicAdd(&csum1[c0 + q + 0], ca.x);
        atomicAdd(&csum1[c0 + q + 1], ca.y);
        atomicAdd(&csum1[c0 + q + 2], ca.z);
        atomicAdd(&csum1[c0 + q + 3], ca.w);
        __syncthreads();

        // compute: rows tid and tid+256, 32 columns in 8 groups of 4
#pragma unroll
        for (int cg = 0; cg < 8; ++cg) {
            float4 xa = st4[tid * 8 + (cg ^ sw)];
            float4 xb = st4[(tid + 256) * 8 + (cg ^ sw)];
            float xav[4] = {xa.x, xa.y, xa.z, xa.w};
            float xbv[4] = {xb.x, xb.y, xb.z, xb.w};
#pragma unroll
            for (int cc = 0; cc < 4; ++cc) {
                const ulonglong2* wp = (const ulonglong2*)&ws[(cg * 4 + cc) * 8];
                ulonglong2 w0 = wp[0], w1 = wp[1], w2 = wp[2], w3 = wp[3];
                unsigned long long xx = packdup(xav[cc]);
                FMA2(a0[0], xx, w0.x); FMA2(a0[1], xx, w0.y);
                FMA2(a0[2], xx, w1.x); FMA2(a0[3], xx, w1.y);
                FMA2(a0[4], xx, w2.x); FMA2(a0[5], xx, w2.y);
                FMA2(a0[6], xx, w3.x); FMA2(a0[7], xx, w3.y);
                unsigned long long yy = packdup(xbv[cc]);
                FMA2(a1[0], yy, w0.x); FMA2(a1[1], yy, w0.y);
                FMA2(a1[2], yy, w1.x); FMA2(a1[3], yy, w1.y);
                FMA2(a1[4], yy, w2.x); FMA2(a1[5], yy, w2.y);
                FMA2(a1[6], yy, w3.x); FMA2(a1[7], yy, w3.y);
            }
        }
    }
    __syncthreads();

    // epilogue: bias/relu + gsl2 + sigmoid for both rows; coalesced S stores
    {
        int gr0 = row0 + tid;
        int gr1 = row0 + tid + 256;
        float z0 = gsl2_b[0], z1 = z0;
#pragma unroll
        for (int p = 0; p < 8; ++p) {
            float b1lo = gsl1_b[2 * p], b1hi = gsl1_b[2 * p + 1];
            float w2lo = gsl2_w[2 * p], w2hi = gsl2_w[2 * p + 1];
            float lo0 = __uint_as_float((unsigned)(a0[p] & 0xFFFFFFFFu));
            float hi0 = __uint_as_float((unsigned)(a0[p] >> 32));
            z0 = fmaf(fmaxf(lo0 + b1lo, 0.f), w2lo, z0);
            z0 = fmaf(fmaxf(hi0 + b1hi, 0.f), w2hi, z0);
            float lo1 = __uint_as_float((unsigned)(a1[p] & 0xFFFFFFFFu));
            float hi1 = __uint_as_float((unsigned)(a1[p] >> 32));
            z1 = fmaf(fmaxf(lo1 + b1lo, 0.f), w2lo, z1);
            z1 = fmaf(fmaxf(hi1 + b1hi, 0.f), w2hi, z1);
        }
        if (gr0 < M_) g_S[(size_t)b * M_ + gr0] = 1.0f / (1.0f + expf(-z0));
        if (gr1 < M_) g_S[(size_t)b * M_ + gr1] = 1.0f / (1.0f + expf(-z1));
    }

    // flush column sums
    atomicAdd(&g_colsum[b * D_ + tid], csum1[tid]);
}

// ---------------- K2: exact k-th largest of S per batch (radix select) ----
// Uniform trip count per block so __ballot_sync never runs under ragged divergence.
__global__ __launch_bounds__(1024) void k2_select(const int* __restrict__ kptr) {
    const int b = blockIdx.x;
    __shared__ unsigned hist[256];
    __shared__ unsigned sh_prefix;
    __shared__ int sh_kneed;

    int kk = kptr ? *kptr : 500;
    if (kk <= 0 || kk > M_) {
        float kf = __int_as_float(kk);
        if (kf >= 1.f && kf <= (float)M_) kk = (int)kf;
        else kk = kk < 1 ? 1 : M_;
    }
    if (kk > M_) kk = M_;

    if (threadIdx.x == 0) { sh_prefix = 0u; sh_kneed = kk; }
    __syncthreads();

    const float* Sb = &g_S[(size_t)b * M_];
    const int NT = 1024;
    const int ITERS = (M_ + NT - 1) / NT;

    for (int pass = 3; pass >= 0; --pass) {
        for (int i = threadIdx.x; i < 256; i += NT) hist[i] = 0u;
        __syncthreads();
        const unsigned pre = sh_prefix;
        const int shift = pass * 8;
        const unsigned himask = (pass == 3) ? 0u : (0xFFFFFFFFu << (shift + 8));

        for (int it = 0; it < ITERS; ++it) {
            const int i = it * NT + threadIdx.x;
            const bool inb = (i < M_);
            unsigned key = inb ? keyOf(Sb[i]) : 0u;
            bool part = inb && (((key ^ pre) & himask) == 0u);
            unsigned act = __ballot_sync(0xFFFFFFFFu, part);
            if (part) {
                int bin = (key >> shift) & 255;
                unsigned peers = __match_any_sync(act, bin);
                int leader = __ffs(peers) - 1;
                if ((int)(threadIdx.x & 31) == leader)
                    atomicAdd(&hist[bin], (unsigned)__popc(peers));
            }
        }
        __syncthreads();
        if (threadIdx.x == 0) {
            int need = sh_kneed;
            unsigned cum = 0; int bin = 0;
            for (int v = 255; v >= 0; --v) {
                if (cum + hist[v] >= (unsigned)need) { bin = v; break; }
                cum += hist[v];
            }
            sh_prefix = pre | ((unsigned)bin << shift);
            sh_kneed = need - (int)cum;
        }
        __syncthreads();
    }
    if (threadIdx.x == 0) g_kth[b] = invKey(sh_prefix);
}

// ---------------- K3: mask output + gather selected indices ---------------
__global__ void k3_mask(float* __restrict__ outmask) {
    const int b = blockIdx.y;
    const int m = blockIdx.x * 256 + threadIdx.x;
    if (m >= M_) return;
    const int idx = b * M_ + m;
    float s = g_S[idx];
    bool sel = s >= g_kth[b];
    outmask[idx] = sel ? 1.f : 0.f;
    if (sel) {
        int pos = atomicAdd(&g_selCount[b], 1);
        if (pos < SEL_CAP) g_selIdx[b * SEL_CAP + pos] = m;
    }
}

// ---------------- K4: selected-row correction (num / den) -----------------
#define RS 16
__global__ __launch_bounds__(256) void k4_selected(
    const float* __restrict__ h,
    const float* __restrict__ att_w, const float* __restrict__ att_b,
    const float* __restrict__ w_w)
{
    __shared__ float hsh[RS][D_];
    __shared__ float efac[RS][NH_];
    __shared__ float aw[D_ * NH_];

    const int b = blockIdx.y;
    const int tid = threadIdx.x;
    for (int i = tid; i < D_ * NH_; i += 256) aw[i] = att_w[i];

    int cnt = g_selCount[b];
    if (cnt > SEL_CAP) cnt = SEL_CAP;
    const int ngroups = (cnt + RS - 1) / RS;
    const float* hb = h + (size_t)b * M_ * D_;

    for (int g = blockIdx.x; g < ngroups; g += gridDim.x) {
        __syncthreads();
        for (int i = tid; i < RS * D_; i += 256) {
            int r = i >> 8, c = i & 255;
            int si = g * RS + r;
            hsh[r][c] = (si < cnt) ? hb[(size_t)g_selIdx[b * SEL_CAP + si] * D_ + c] : 0.f;
        }
        __syncthreads();
        if (tid < RS * NH_) {
            int r = tid >> 3, hd = tid & 7;
            float s = 0.f;
            for (int c = 0; c < D_; c++) s = fmaf(hsh[r][c], aw[c * NH_ + hd], s);
            float a = fmaxf(s + att_b[hd], 0.f);
            efac[r][hd] = (g * RS + r < cnt) ? (expf(a) - 1.f) : 0.f;
        }
        __syncthreads();

        const int e = tid;
        float acc[RS];
#pragma unroll
        for (int r = 0; r < RS; r++) acc[r] = 0.f;
        for (int c = 0; c < D_; c++) {
            float w = __ldg(&w_w[c * OUT_ + e]);
#pragma unroll
            for (int r = 0; r < RS; r++) acc[r] = fmaf(hsh[r][c], w, acc[r]);
        }
        const int hd = e >> 5;
        float s = 0.f;
#pragma unroll
        for (int r = 0; r < RS; r++) s = fmaf(efac[r][hd], acc[r], s);
        atomicAdd(&g_num[b * OUT_ + e], s);
        if (tid < NH_) {
            float d = 0.f;
#pragma unroll
            for (int r = 0; r < RS; r++) d += efac[r][tid];
            atomicAdd(&g_den[b * NH_ + tid], d);
        }
    }
}

// ---------------- K5: base term + Q_res + combine + normalize -------------
__global__ __launch_bounds__(256) void k5_final(
    const float* __restrict__ w_w,
    const float* __restrict__ res_w, const float* __restrict__ res_b,
    float* __restrict__ out)
{
    const int b = blockIdx.x;
    const int e = threadIdx.x;
    __shared__ float cs[D_];
    __shared__ float red[256];

    cs[e] = g_colsum[b * D_ + e];
    __syncthreads();

    float base = 0.f, qr = 0.f;
#pragma unroll 4
    for (int c = 0; c < D_; c++) {
        float x = cs[c];
        base = fmaf(x, __ldg(&w_w[c * OUT_ + e]), base);
        qr   = fmaf(x, __ldg(&res_w[c * OUT_ + e]), qr);
    }
    qr *= (1.0f / (float)M_);
    float Qres = fmaxf(qr + res_b[e], 0.f);
    float den = (float)M_ + g_den[b * NH_ + (e >> 5)];
    float ov = (base + g_num[b * OUT_ + e]) / den;
    float v = fmaxf(ov + Qres, 0.f);

    red[e] = v; __syncthreads();
    for (int s = 128; s > 0; s >>= 1) {
        if (e < s) red[e] += red[e + s];
        __syncthreads();
    }
    float mean = red[0] * (1.0f / 256.0f);
    __syncthreads();
    float dm = v - mean;
    red[e] = dm * dm; __syncthreads();
    for (int s = 128; s > 0; s >>= 1) {
        if (e < s) red[e] += red[e + s];
        __syncthreads();
    }
    float var = red[0] * (1.0f / 256.0f);
    out[b * OUT_ + e] = dm * rsqrtf(var + 1e-8f);
}

// ---------------- launch -----------------
#define K1_SMEM (65536 + 2048 + 1024)

extern "C" void kernel_launch(void* const* d_in, const int* in_sizes, int n_in,
                              void* d_out, int out_size)
{
    const float* h      = (const float*)d_in[0];
    const float* att_w  = (const float*)d_in[1];
    const float* att_b  = (const float*)d_in[2];
    const float* w_w    = (const float*)d_in[3];
    const float* res_w  = (const float*)d_in[4];
    const float* res_b  = (const float*)d_in[5];
    const float* gsl1_w = (const float*)d_in[6];
    const float* gsl1_b = (const float*)d_in[7];
    const float* gsl2_w = (const float*)d_in[8];
    const float* gsl2_b = (const float*)d_in[9];
    const int*   kptr   = (n_in > 10) ? (const int*)d_in[10] : nullptr;

    float* out  = (float*)d_out;              // [B, 1, OUT] -> 2048 floats
    float* mask = out + B_ * OUT_;            // [B, 1, M]   -> 400000 floats

    cudaFuncSetAttribute(k1_gate, cudaFuncAttributeMaxDynamicSharedMemorySize, K1_SMEM);

    // launches 1-3: zeroing (k1 is launch #4 for ncu)
    z_colsum<<<8, 256>>>();
    z_num<<<8, 256>>>();
    z_misc<<<1, 128>>>();

    {
        dim3 grid(TILES_PER_B, B_);   // 98 x 8 = 784 blocks, 3/SM -> 1.77 waves
        k1_gate<<<grid, 256, K1_SMEM>>>(h, gsl1_w, gsl1_b, gsl2_w, gsl2_b);
    }
    k2_select<<<B_, 1024>>>(kptr);
    {
        dim3 grid((M_ + 255) / 256, B_);
        k3_mask<<<grid, 256>>>(mask);
    }
    {
        dim3 grid(16, B_);
        k4_selected<<<grid, 256>>>(h, att_w, att_b, w_w);
    }
    k5_final<<<B_, 256>>>(w_w, res_w, res_b, out);
}

// round 7
// speedup vs baseline: 1.3727x; 1.1581x over previous
#include <cuda_runtime.h>
#include <cuda_bf16.h>
#include <stdint.h>

// Problem constants (fixed by the dataset)
#define B_   8
#define M_   50000
#define D_   256
#define NH_  8
#define GH_  16
#define OUT_ 256
#define SEL_CAP 2048

#define TILE_ROWS 512
#define TILES_PER_B 98               // ceil(50000/512)

// ---------------- scratch (device globals; no allocations) ----------------
__device__ __align__(16) float g_S[B_ * M_];
__device__ __align__(16) float g_colsum[B_ * D_];
__device__ float g_kth[B_];
__device__ int   g_selCount[B_];
__device__ int   g_selIdx[B_ * SEL_CAP];
__device__ __align__(16) float g_num[B_ * OUT_];
__device__ float g_den[B_ * NH_];
__device__ __align__(16) float g_v[B_ * OUT_];

// ---------------- helpers ----------------
__device__ __forceinline__ unsigned keyOf(float x) {
    unsigned u = __float_as_uint(x);
    return (u & 0x80000000u) ? ~u : (u | 0x80000000u);
}
__device__ __forceinline__ float invKey(unsigned k) {
    unsigned u = (k & 0x80000000u) ? (k & 0x7FFFFFFFu) : ~k;
    return __uint_as_float(u);
}

// f32x2 packed FMA (Blackwell sm_103a)
#define FMA2(acc, a, b) asm("fma.rn.f32x2 %0, %1, %2, %0;" : "+l"(acc) : "l"(a), "l"(b))
__device__ __forceinline__ unsigned long long packdup(float x) {
    unsigned long long r;
    unsigned xu = __float_as_uint(x);
    asm("mov.b64 %0, {%1, %1};" : "=l"(r) : "r"(xu));
    return r;
}
__device__ __forceinline__ float f2lo(unsigned long long v) {
    return __uint_as_float((unsigned)(v & 0xFFFFFFFFu));
}
__device__ __forceinline__ float f2hi(unsigned long long v) {
    return __uint_as_float((unsigned)(v >> 32));
}

// ---------------- Z: zero scratch (3 launches; k1 is launch #4) ------------
__global__ void z_colsum() {
    int i = blockIdx.x * 256 + threadIdx.x;
    if (i < B_ * D_) g_colsum[i] = 0.f;
}
__global__ void z_num() {
    int i = blockIdx.x * 256 + threadIdx.x;
    if (i < B_ * OUT_) g_num[i] = 0.f;
}
__global__ void z_misc() {
    int i = threadIdx.x;
    if (i < B_ * NH_) g_den[i] = 0.f;
    if (i < B_)       g_selCount[i] = 0;
}

// ---------------- K1: gate scores S + column sums --------------------------
// Tile = 512 rows. 256 threads: thread t owns rows (t>>2)*8..+7 and hidden
// units 4*(t&3)..4*(t&3)+3 (2 u64 f32x2 accumulators per row).
// Per 32-col chunk: stage via coalesced LDG.128 into XOR-swizzled smem
// (key = (row>>3)&7 -> the 8 rows a warp touches per step hit 8 distinct
// bank groups; 4-lane broadcast across the hidden split). Weights: 1 LDS.128
// per column per thread serving 8 rows. Column sums fused into staging.
// LSU/FMA2 lane-op ratio ~0.25 (was ~0.70).
__global__ __launch_bounds__(256, 3) void k1_gate(
    const float* __restrict__ h,
    const float* __restrict__ gsl1_w, const float* __restrict__ gsl1_b,
    const float* __restrict__ gsl2_w, const float* __restrict__ gsl2_b)
{
    extern __shared__ __align__(16) unsigned char smraw[];
    float4* st4 = (float4*)smraw;                                   // 512*8 float4 = 64KB
    unsigned long long* ws = (unsigned long long*)(smraw + 65536);  // 256 u64 = 2KB
    float* csum1 = (float*)(smraw + 65536 + 2048);                  // 256 f = 1KB

    const int tid  = threadIdx.x;
    const int b    = blockIdx.y;
    const int row0 = blockIdx.x * TILE_ROWS;
    const int hseg = tid & 3;            // hidden units 4*hseg .. 4*hseg+3
    const int rg   = tid >> 2;           // row group: rows rg*8 .. rg*8+7
    const int sw8  = tid & 7;            // staging column-octet
    const int q    = sw8 << 2;

    csum1[tid] = 0.f;

    const float* hb = h + (size_t)b * M_ * D_;
    const unsigned long long* gw = (const unsigned long long*)gsl1_w; // [256 cols][8 u64]

    unsigned long long acc[8][2];
#pragma unroll
    for (int r = 0; r < 8; r++) { acc[r][0] = 0ULL; acc[r][1] = 0ULL; }

    for (int ch = 0; ch < 8; ++ch) {
        const int c0 = ch * 32;
        __syncthreads();                 // st4/ws reusable; csum1 init visible

        ws[tid] = gw[c0 * 8 + tid];      // 32 cols x 8 u64 pairs

        // stage 512 rows x 32 cols; column partials accumulated in registers
        float4 ca = make_float4(0.f, 0.f, 0.f, 0.f);
#pragma unroll
        for (int j = 0; j < 16; ++j) {
            int f = tid + 256 * j;       // f&7 == sw8 (fixed octet)
            int r = f >> 3;
            int gr = row0 + r;
            float4 v = make_float4(0.f, 0.f, 0.f, 0.f);
            if (gr < M_) v = *(const float4*)(hb + (size_t)gr * D_ + c0 + q);
            ca.x += v.x; ca.y += v.y; ca.z += v.z; ca.w += v.w;
            st4[r * 8 + (sw8 ^ ((r >> 3) & 7))] = v;
        }
        atomicAdd(&csum1[c0 + q + 0], ca.x);
        atomicAdd(&csum1[c0 + q + 1], ca.y);
        atomicAdd(&csum1[c0 + q + 2], ca.z);
        atomicAdd(&csum1[c0 + q + 3], ca.w);
        __syncthreads();

        // compute: 8 col-groups of 4; per cg: 4 w-LDS.128 + 8 x-LDS.128 + 64 FMA2
#pragma unroll
        for (int cg = 0; cg < 8; ++cg) {
            ulonglong2 w0 = *(const ulonglong2*)&ws[(cg * 4 + 0) * 8 + hseg * 2];
            ulonglong2 w1 = *(const ulonglong2*)&ws[(cg * 4 + 1) * 8 + hseg * 2];
            ulonglong2 w2 = *(const ulonglong2*)&ws[(cg * 4 + 2) * 8 + hseg * 2];
            ulonglong2 w3 = *(const ulonglong2*)&ws[(cg * 4 + 3) * 8 + hseg * 2];
            const int slot = cg ^ (rg & 7);
#pragma unroll
            for (int rr = 0; rr < 8; ++rr) {
                float4 x4 = st4[(rg * 8 + rr) * 8 + slot];
                unsigned long long xx;
                xx = packdup(x4.x); FMA2(acc[rr][0], xx, w0.x); FMA2(acc[rr][1], xx, w0.y);
                xx = packdup(x4.y); FMA2(acc[rr][0], xx, w1.x); FMA2(acc[rr][1], xx, w1.y);
                xx = packdup(x4.z); FMA2(acc[rr][0], xx, w2.x); FMA2(acc[rr][1], xx, w2.y);
                xx = packdup(x4.w); FMA2(acc[rr][0], xx, w3.x); FMA2(acc[rr][1], xx, w3.y);
            }
        }
    }
    __syncthreads();

    // epilogue: per-row partial z over this thread's 4 hidden units,
    // reduce across the 4 hseg lanes (consecutive), sigmoid, packed store.
    {
        const int u0 = 4 * hseg;
        const float b1a = gsl1_b[u0 + 0], b1b = gsl1_b[u0 + 1];
        const float b1c = gsl1_b[u0 + 2], b1d = gsl1_b[u0 + 3];
        const float w2a = gsl2_w[u0 + 0], w2b = gsl2_w[u0 + 1];
        const float w2c = gsl2_w[u0 + 2], w2d = gsl2_w[u0 + 3];

        float zr[8];
#pragma unroll
        for (int rr = 0; rr < 8; ++rr) {
            float z = 0.f;
            z = fmaf(fmaxf(f2lo(acc[rr][0]) + b1a, 0.f), w2a, z);
            z = fmaf(fmaxf(f2hi(acc[rr][0]) + b1b, 0.f), w2b, z);
            z = fmaf(fmaxf(f2lo(acc[rr][1]) + b1c, 0.f), w2c, z);
            z = fmaf(fmaxf(f2hi(acc[rr][1]) + b1d, 0.f), w2d, z);
            z += __shfl_xor_sync(0xFFFFFFFFu, z, 1);
            z += __shfl_xor_sync(0xFFFFFFFFu, z, 2);
            zr[rr] = z;
        }
        if (hseg == 0) {
            const float b2 = gsl2_b[0];
            const int base = row0 + rg * 8;
            if (base + 8 <= M_) {
                float4 s0, s1;
                s0.x = 1.0f / (1.0f + expf(-(zr[0] + b2)));
                s0.y = 1.0f / (1.0f + expf(-(zr[1] + b2)));
                s0.z = 1.0f / (1.0f + expf(-(zr[2] + b2)));
                s0.w = 1.0f / (1.0f + expf(-(zr[3] + b2)));
                s1.x = 1.0f / (1.0f + expf(-(zr[4] + b2)));
                s1.y = 1.0f / (1.0f + expf(-(zr[5] + b2)));
                s1.z = 1.0f / (1.0f + expf(-(zr[6] + b2)));
                s1.w = 1.0f / (1.0f + expf(-(zr[7] + b2)));
                *(float4*)&g_S[(size_t)b * M_ + base] = s0;
                *(float4*)&g_S[(size_t)b * M_ + base + 4] = s1;
            }
        }
    }

    // flush column sums
    atomicAdd(&g_colsum[b * D_ + tid], csum1[tid]);
}

// ---------------- K2: exact k-th largest per batch + mask + gather --------
// Uniform trip count for the ballot loops; mask/gather epilogue fused in.
__global__ __launch_bounds__(1024) void k2_select(const int* __restrict__ kptr,
                                                  float* __restrict__ outmask)
{
    const int b = blockIdx.x;
    __shared__ unsigned hist[256];
    __shared__ unsigned sh_prefix;
    __shared__ int sh_kneed;

    int kk = kptr ? *kptr : 500;
    if (kk <= 0 || kk > M_) {
        float kf = __int_as_float(kk);
        if (kf >= 1.f && kf <= (float)M_) kk = (int)kf;
        else kk = kk < 1 ? 1 : M_;
    }
    if (kk > M_) kk = M_;

    if (threadIdx.x == 0) { sh_prefix = 0u; sh_kneed = kk; }
    __syncthreads();

    const float* Sb = &g_S[(size_t)b * M_];
    const int NT = 1024;
    const int ITERS = (M_ + NT - 1) / NT;

    for (int pass = 3; pass >= 0; --pass) {
        for (int i = threadIdx.x; i < 256; i += NT) hist[i] = 0u;
        __syncthreads();
        const unsigned pre = sh_prefix;
        const int shift = pass * 8;
        const unsigned himask = (pass == 3) ? 0u : (0xFFFFFFFFu << (shift + 8));

        for (int it = 0; it < ITERS; ++it) {
            const int i = it * NT + threadIdx.x;
            const bool inb = (i < M_);
            unsigned key = inb ? keyOf(Sb[i]) : 0u;
            bool part = inb && (((key ^ pre) & himask) == 0u);
            unsigned act = __ballot_sync(0xFFFFFFFFu, part);
            if (part) {
                int bin = (key >> shift) & 255;
                unsigned peers = __match_any_sync(act, bin);
                int leader = __ffs(peers) - 1;
                if ((int)(threadIdx.x & 31) == leader)
                    atomicAdd(&hist[bin], (unsigned)__popc(peers));
            }
        }
        __syncthreads();
        if (threadIdx.x == 0) {
            int need = sh_kneed;
            unsigned cum = 0; int bin = 0;
            for (int v = 255; v >= 0; --v) {
                if (cum + hist[v] >= (unsigned)need) { bin = v; break; }
                cum += hist[v];
            }
            sh_prefix = pre | ((unsigned)bin << shift);
            sh_kneed = need - (int)cum;
        }
        __syncthreads();
    }
    const float kth = invKey(sh_prefix);
    if (threadIdx.x == 0) g_kth[b] = kth;

    // fused mask + gather (no warp-sync ops: ragged loop is fine)
    for (int i = threadIdx.x; i < M_; i += NT) {
        float s = Sb[i];
        bool sel = s >= kth;
        outmask[b * M_ + i] = sel ? 1.f : 0.f;
        if (sel) {
            int pos = atomicAdd(&g_selCount[b], 1);
            if (pos < SEL_CAP) g_selIdx[b * SEL_CAP + pos] = i;
        }
    }
}

// ---------------- K4: selected-row correction (num / den) -----------------
#define RS 16
__global__ __launch_bounds__(256) void k4_selected(
    const float* __restrict__ h,
    const float* __restrict__ att_w, const float* __restrict__ att_b,
    const float* __restrict__ w_w)
{
    __shared__ __align__(16) float hsh[RS][D_];
    __shared__ float efac[RS][NH_];
    __shared__ float aw[D_ * NH_];

    const int b = blockIdx.y;
    const int tid = threadIdx.x;
    for (int i = tid; i < D_ * NH_; i += 256) aw[i] = att_w[i];

    int cnt = g_selCount[b];
    if (cnt > SEL_CAP) cnt = SEL_CAP;
    const int ngroups = (cnt + RS - 1) / RS;
    const float* hb = h + (size_t)b * M_ * D_;

    for (int g = blockIdx.x; g < ngroups; g += gridDim.x) {
        __syncthreads();
        // stage 16 selected rows as float4 (coalesced per row)
        for (int i = tid; i < RS * (D_ / 4); i += 256) {
            int r = i >> 6, c4 = (i & 63) << 2;
            int si = g * RS + r;
            float4 v = make_float4(0.f, 0.f, 0.f, 0.f);
            if (si < cnt)
                v = *(const float4*)(hb + (size_t)g_selIdx[b * SEL_CAP + si] * D_ + c4);
            *(float4*)&hsh[r][c4] = v;
        }
        __syncthreads();
        if (tid < RS * NH_) {
            int r = tid >> 3, hd = tid & 7;
            float s = 0.f;
            for (int c = 0; c < D_; c++) s = fmaf(hsh[r][c], aw[c * NH_ + hd], s);
            float a = fmaxf(s + att_b[hd], 0.f);
            efac[r][hd] = (g * RS + r < cnt) ? (expf(a) - 1.f) : 0.f;
        }
        __syncthreads();

        const int e = tid;
        float acc[RS];
#pragma unroll
        for (int r = 0; r < RS; r++) acc[r] = 0.f;
        for (int c4 = 0; c4 < D_; c4 += 4) {
            float w0 = __ldg(&w_w[(c4 + 0) * OUT_ + e]);
            float w1 = __ldg(&w_w[(c4 + 1) * OUT_ + e]);
            float w2 = __ldg(&w_w[(c4 + 2) * OUT_ + e]);
            float w3 = __ldg(&w_w[(c4 + 3) * OUT_ + e]);
#pragma unroll
            for (int r = 0; r < RS; r++) {
                float4 hv = *(const float4*)&hsh[r][c4];
                float a = acc[r];
                a = fmaf(hv.x, w0, a);
                a = fmaf(hv.y, w1, a);
                a = fmaf(hv.z, w2, a);
                a = fmaf(hv.w, w3, a);
                acc[r] = a;
            }
        }
        const int hd = e >> 5;
        float s = 0.f;
#pragma unroll
        for (int r = 0; r < RS; r++) s = fmaf(efac[r][hd], acc[r], s);
        atomicAdd(&g_num[b * OUT_ + e], s);
        if (tid < NH_) {
            float d = 0.f;
#pragma unroll
            for (int r = 0; r < RS; r++) d += efac[r][tid];
            atomicAdd(&g_den[b * NH_ + tid], d);
        }
    }
}

// ---------------- K5a: base term + Q_res + combine (col-parallel) ---------
// grid (8, B_): block computes 32 outputs; 8 threads per output, 32 cols each.
__global__ __launch_bounds__(256) void k5a(
    const float* __restrict__ w_w,
    const float* __restrict__ res_w, const float* __restrict__ res_b)
{
    const int b = blockIdx.y;
    const int e = blockIdx.x * 32 + (threadIdx.x >> 3);
    const int l8 = threadIdx.x & 7;
    __shared__ float cs[D_];
    cs[threadIdx.x] = g_colsum[b * D_ + threadIdx.x];
    __syncthreads();

    float base = 0.f, qr = 0.f;
#pragma unroll 8
    for (int i = 0; i < 32; i++) {
        int c = l8 + 8 * i;
        float x = cs[c];
        base = fmaf(x, __ldg(&w_w[c * OUT_ + e]), base);
        qr   = fmaf(x, __ldg(&res_w[c * OUT_ + e]), qr);
    }
#pragma unroll
    for (int m = 1; m < 8; m <<= 1) {
        base += __shfl_xor_sync(0xFFFFFFFFu, base, m);
        qr   += __shfl_xor_sync(0xFFFFFFFFu, qr, m);
    }
    if (l8 == 0) {
        float Qres = fmaxf(qr * (1.0f / (float)M_) + res_b[e], 0.f);
        float den = (float)M_ + g_den[b * NH_ + (e >> 5)];
        float ov = (base + g_num[b * OUT_ + e]) / den;
        g_v[b * OUT_ + e] = fmaxf(ov + Qres, 0.f);
    }
}

// ---------------- K5b: layernorm of the 256-vector ------------------------
__global__ __launch_bounds__(256) void k5b(float* __restrict__ out)
{
    const int b = blockIdx.x;
    const int e = threadIdx.x;
    __shared__ float red[256];

    float v = g_v[b * OUT_ + e];
    red[e] = v; __syncthreads();
    for (int s = 128; s > 0; s >>= 1) {
        if (e < s) red[e] += red[e + s];
        __syncthreads();
    }
    float mean = red[0] * (1.0f / 256.0f);
    __syncthreads();
    float dm = v - mean;
    red[e] = dm * dm; __syncthreads();
    for (int s = 128; s > 0; s >>= 1) {
        if (e < s) red[e] += red[e + s];
        __syncthreads();
    }
    float var = red[0] * (1.0f / 256.0f);
    out[b * OUT_ + e] = dm * rsqrtf(var + 1e-8f);
}

// ---------------- launch -----------------
#define K1_SMEM (65536 + 2048 + 1024)

extern "C" void kernel_launch(void* const* d_in, const int* in_sizes, int n_in,
                              void* d_out, int out_size)
{
    const float* h      = (const float*)d_in[0];
    const float* att_w  = (const float*)d_in[1];
    const float* att_b  = (const float*)d_in[2];
    const float* w_w    = (const float*)d_in[3];
    const float* res_w  = (const float*)d_in[4];
    const float* res_b  = (const float*)d_in[5];
    const float* gsl1_w = (const float*)d_in[6];
    const float* gsl1_b = (const float*)d_in[7];
    const float* gsl2_w = (const float*)d_in[8];
    const float* gsl2_b = (const float*)d_in[9];
    const int*   kptr   = (n_in > 10) ? (const int*)d_in[10] : nullptr;

    float* out  = (float*)d_out;              // [B, 1, OUT] -> 2048 floats
    float* mask = out + B_ * OUT_;            // [B, 1, M]   -> 400000 floats

    cudaFuncSetAttribute(k1_gate, cudaFuncAttributeMaxDynamicSharedMemorySize, K1_SMEM);

    // launches 1-3: zeroing (k1 is launch #4 for ncu)
    z_colsum<<<8, 256>>>();
    z_num<<<8, 256>>>();
    z_misc<<<1, 128>>>();

    {
        dim3 grid(TILES_PER_B, B_);   // 98 x 8 = 784 blocks, 3/SM
        k1_gate<<<grid, 256, K1_SMEM>>>(h, gsl1_w, gsl1_b, gsl2_w, gsl2_b);
    }
    k2_select<<<B_, 1024>>>(kptr, mask);
    {
        dim3 grid(64, B_);
        k4_selected<<<grid, 256>>>(h, att_w, att_b, w_w);
    }
    {
        dim3 grid(8, B_);
        k5a<<<grid, 256>>>(w_w, res_w, res_b);
    }
    k5b<<<B_, 256>>>(out);
}